// round 13
// baseline (speedup 1.0000x reference)
#include <cuda_runtime.h>
#include <cuda_fp16.h>

// APPNP, K=10. State g = norm ⊙ h in fp16 (row = 64 halves = 128B).
//   g_{t+1} = 0.9*norm^2 * (sum_{(s->v)} g_t[s]) + anchor, anchor = 0.1*norm*feat
// Final: h = 0.9*norm*agg + 0.1*feat (fp32).
//
// Round 13: block-cooperative id staging. 8 warps/block own 8 consecutive
// nodes; their CSR id ranges are contiguous (counting sort), so the block
// loads rowptr[9] + the whole id range into SMEM coalesced ONCE, replacing
// each warp's serial rowptr(260cyc)->id(260cyc) chain legs with LDS (29cyc).
// Row gather unchanged from round-8 best (SIMT-4: one LDG.128 = 4 fp16 rows).

#define NMAX  100000
#define DF    64
#define DF2   (DF / 2)
#define EMAX  1000000
#define EPAD  (EMAX + 4 * NMAX + 32)
#define KITER 10
#define TILE  256
#define NTILE ((NMAX + TILE - 1) / TILE)   // 391
#define NPB   8                            // nodes per block (= warps/block)
#define IDCAP 1536                         // smem id buffer (ints)

__device__ uint4 g_a[(NMAX + 1) * 8];
__device__ uint4 g_b[(NMAX + 1) * 8];
__device__ uint4 g_anchor[(NMAX + 1) * 8];  // 0.1*norm*feat in fp16
__device__ float g_norm[NMAX];
__device__ int   g_deg[NMAX];
__device__ int   g_rowptr[NMAX + 1];        // padded-degree prefix
__device__ int   g_cursor[NMAX];
__device__ int   g_srcs[EPAD];
__device__ int   g_part[NTILE];

// ---------------------------------------------------------------- build ----

__global__ void k_zero(int n) {
    int i = blockIdx.x * blockDim.x + threadIdx.x;
    if (i < n) { g_deg[i] = 0; g_cursor[i] = 0; }
}

__global__ void k_deg(const int* __restrict__ dst, int e) {
    int i = blockIdx.x * blockDim.x + threadIdx.x;
    if (i < e) atomicAdd(&g_deg[dst[i]], 1);
}

__global__ void k_scan_part(int n) {
    __shared__ int sh[TILE];
    int t = threadIdx.x;
    int i = blockIdx.x * TILE + t;
    int d = (i < n) ? g_deg[i] : 0;
    sh[t] = (d + 3) & ~3;
    __syncthreads();
    for (int off = TILE >> 1; off > 0; off >>= 1) {
        if (t < off) sh[t] += sh[t + off];
        __syncthreads();
    }
    if (t == 0) g_part[blockIdx.x] = sh[0];
}

__global__ void k_scan_top(int nb) {
    __shared__ int sh[512];
    int t = threadIdx.x;
    int v = (t < nb) ? g_part[t] : 0;
    sh[t] = v;
    __syncthreads();
    for (int off = 1; off < 512; off <<= 1) {
        int x = (t >= off) ? sh[t - off] : 0;
        __syncthreads();
        sh[t] += x;
        __syncthreads();
    }
    if (t < nb) g_part[t] = sh[t] - v;
}

__global__ void k_scan_fin(int n) {
    __shared__ int sh[TILE];
    int t = threadIdx.x;
    int i = blockIdx.x * TILE + t;
    int d    = (i < n) ? g_deg[i] : 0;
    int dpad = (d + 3) & ~3;
    sh[t] = dpad;
    __syncthreads();
    for (int off = 1; off < TILE; off <<= 1) {
        int x = (t >= off) ? sh[t - off] : 0;
        __syncthreads();
        sh[t] += x;
        __syncthreads();
    }
    if (i < n) {
        g_rowptr[i] = sh[t] - dpad + g_part[blockIdx.x];
        g_norm[i]   = rsqrtf(fmaxf((float)d, 1.0f));
        if (i == n - 1) g_rowptr[n] = sh[t] + g_part[blockIdx.x];
    }
}

__global__ void k_fill(const int* __restrict__ src,
                       const int* __restrict__ dst, int e) {
    int i = blockIdx.x * blockDim.x + threadIdx.x;
    if (i < e) {
        int d = dst[i];
        int pos = g_rowptr[d] + atomicAdd(&g_cursor[d], 1);
        g_srcs[pos] = src[i];
    }
}

__global__ void k_pad(int n) {
    int i = blockIdx.x * blockDim.x + threadIdx.x;
    if (i < n) {
        int s  = g_rowptr[i] + g_deg[i];
        int e2 = g_rowptr[i + 1];
        for (int j = s; j < e2; ++j) g_srcs[j] = n;
    }
}

__global__ void k_init(const float* __restrict__ feat, int n) {
    int i = blockIdx.x * blockDim.x + threadIdx.x;   // half2 index
    int tot = (n + 1) * DF2;
    if (i >= tot) return;
    __half2* pa = reinterpret_cast<__half2*>(g_a);
    __half2* pb = reinterpret_cast<__half2*>(g_b);
    __half2* pn = reinterpret_cast<__half2*>(g_anchor);
    int row = i >> 5;
    if (row < n) {
        float nm = g_norm[row];
        float2 f = reinterpret_cast<const float2*>(feat)[i];
        pa[i] = __floats2half2_rn(nm * f.x, nm * f.y);
        pn[i] = __floats2half2_rn(0.1f * nm * f.x, 0.1f * nm * f.y);
    } else {
        __half2 z = __floats2half2_rn(0.f, 0.f);
        pa[i] = z; pb[i] = z; pn[i] = z;
    }
}

// ----------------------------------------------------------------- loop ----

__device__ __forceinline__ void acc_row(const uint4& r, float* acc) {
    const __half2* h = reinterpret_cast<const __half2*>(&r);
    #pragma unroll
    for (int j = 0; j < 4; ++j) {
        float2 w = __half22float2(h[j]);
        acc[2 * j]     += w.x;
        acc[2 * j + 1] += w.y;
    }
}

// Gather loop over one node's padded id list (ids may point at SMEM or GMEM).
__device__ __forceinline__ void gather_node(const int* __restrict__ ids,
                                            int idx, int end,
                                            const uint4* __restrict__ gin,
                                            int slot, int oct, float* acc) {
    for (; idx + 8 <= end; idx += 8) {
        int s0 = ids[idx + slot];
        int s1 = ids[idx + 4 + slot];
        uint4 r0 = gin[s0 * 8 + oct];
        uint4 r1 = gin[s1 * 8 + oct];
        acc_row(r0, acc);
        acc_row(r1, acc);
    }
    if (idx < end) {
        int s0 = ids[idx + slot];
        uint4 r0 = gin[s0 * 8 + oct];
        acc_row(r0, acc);
    }
}

// Block = 8 warps = 8 consecutive nodes. Prologue: coalesced staging of
// rowptr[9] + the block's contiguous id range into SMEM. Then each warp
// gathers its node with LDS-latency ids.
__global__ void __launch_bounds__(256) k_prop(
        const float* __restrict__ feat, float* __restrict__ out,
        int n, int flip, int last) {
    __shared__ int sh_rp[NPB + 1];
    __shared__ int sh_ids[IDCAP];

    int tid  = threadIdx.x;
    int w    = tid >> 5;
    int lane = tid & 31;
    int slot = lane >> 3;
    int oct  = lane & 7;
    int b0   = blockIdx.x * NPB;

    if (tid <= NPB) {
        int node = b0 + tid;
        sh_rp[tid] = g_rowptr[node < n ? node : n];
    }
    __syncthreads();

    int base  = sh_rp[0];
    int total = sh_rp[NPB] - base;
    bool fits = (total <= IDCAP);
    if (fits) {
        for (int i = tid; i < total; i += 256)
            sh_ids[i] = g_srcs[base + i];
    }
    __syncthreads();

    const uint4* gin  = flip ? g_b : g_a;
    uint4*       gout = flip ? g_a : g_b;

    int v = b0 + w;
    if (v >= n) return;

    int idx = sh_rp[w];
    int end = sh_rp[w + 1];

    float acc[8];
    #pragma unroll
    for (int j = 0; j < 8; ++j) acc[j] = 0.f;

    if (fits) {
        gather_node(sh_ids, idx - base, end - base, gin, slot, oct, acc);
    } else {
        gather_node(g_srcs, idx, end, gin, slot, oct, acc);
    }

    #pragma unroll
    for (int j = 0; j < 8; ++j) {
        acc[j] += __shfl_xor_sync(0xffffffff, acc[j], 8);
        acc[j] += __shfl_xor_sync(0xffffffff, acc[j], 16);
    }

    float nm = __ldg(&g_norm[v]);

    if (!last) {
        if (lane < 8) {
            float c1 = 0.9f * nm * nm;
            uint4 an = g_anchor[v * 8 + oct];
            const __half2* ah = reinterpret_cast<const __half2*>(&an);
            uint4 o;
            __half2* oh = reinterpret_cast<__half2*>(&o);
            #pragma unroll
            for (int j = 0; j < 4; ++j) {
                float2 a2 = __half22float2(ah[j]);
                oh[j] = __floats2half2_rn(c1 * acc[2 * j]     + a2.x,
                                          c1 * acc[2 * j + 1] + a2.y);
            }
            gout[v * 8 + oct] = o;
        }
    } else {
        if (lane < 8) {
            float c1 = 0.9f * nm;
            const float4* fr = reinterpret_cast<const float4*>(feat + v * DF);
            float4* orow = reinterpret_cast<float4*>(out + v * DF);
            float4 f0 = fr[oct * 2];
            float4 f1 = fr[oct * 2 + 1];
            float4 o0, o1;
            o0.x = c1 * acc[0] + 0.1f * f0.x;
            o0.y = c1 * acc[1] + 0.1f * f0.y;
            o0.z = c1 * acc[2] + 0.1f * f0.z;
            o0.w = c1 * acc[3] + 0.1f * f0.w;
            o1.x = c1 * acc[4] + 0.1f * f1.x;
            o1.y = c1 * acc[5] + 0.1f * f1.y;
            o1.z = c1 * acc[6] + 0.1f * f1.z;
            o1.w = c1 * acc[7] + 0.1f * f1.w;
            orow[oct * 2]     = o0;
            orow[oct * 2 + 1] = o1;
        }
    }
}

// ---------------------------------------------------------------- launch ----

extern "C" void kernel_launch(void* const* d_in, const int* in_sizes, int n_in,
                              void* d_out, int out_size) {
    const float* feat = (const float*)d_in[0];
    const int*   src  = (const int*)d_in[1];
    const int*   dst  = (const int*)d_in[2];
    float*       out  = (float*)d_out;

    int n = in_sizes[0] / DF;   // 100000
    int e = in_sizes[1];        // 1000000

    const int T = 256;
    int blk_n = (n + T - 1) / T;
    int blk_e = (e + T - 1) / T;
    int blk_i = ((n + 1) * DF2 + T - 1) / T;
    int blk_p = (n + NPB - 1) / NPB;        // 8 nodes per block
    int nb    = (n + TILE - 1) / TILE;

    // CSR build with 4-padded segments (round-8 verbatim)
    k_zero<<<blk_n, T>>>(n);
    k_deg<<<blk_e, T>>>(dst, e);
    k_scan_part<<<nb, TILE>>>(n);
    k_scan_top<<<1, 512>>>(nb);
    k_scan_fin<<<nb, TILE>>>(n);
    k_fill<<<blk_e, T>>>(src, dst, e);
    k_pad<<<blk_n, T>>>(n);
    k_init<<<blk_i, T>>>(feat, n);

    // Propagation: ping-pong g_a <-> g_b, final iter writes d_out (fp32).
    for (int t = 0; t < KITER; ++t) {
        int flip = t & 1;
        int last = (t == KITER - 1);
        k_prop<<<blk_p, T>>>(feat, out, n, flip, last);
    }
}

// round 14
// speedup vs baseline: 1.1855x; 1.1855x over previous
#include <cuda_runtime.h>
#include <cuda_fp16.h>

// APPNP, K=10. State g = norm ⊙ h in fp16 (row = 64 halves = 128B).
//   g_{t+1} = 0.9*norm^2 * (sum_{(s->v)} g_t[s]) + anchor, anchor = 0.1*norm*feat
// Final: h = 0.9*norm*agg + 0.1*feat (fp32).
//
// Round 14: loop reverted to round-8 best (276.5us) VERBATIM; build attacked:
//  - k_fill: cursor pre-seeded with rowptr (in k_scan_fin), so fill is one
//    random atomic instead of random read + random atomic (17us -> ~11us).
//  - k_scan_top: shuffle-based scan, 2 barriers instead of 18 (4.5 -> ~1.5us).
//  - k_pad: uses cursor (== rowptr+deg post-fill) directly.

#define NMAX  100000
#define DF    64
#define DF2   (DF / 2)
#define EMAX  1000000
#define EPAD  (EMAX + 4 * NMAX + 32)
#define KITER 10
#define TILE  256
#define NTILE ((NMAX + TILE - 1) / TILE)   // 391

__device__ uint4 g_a[(NMAX + 1) * 8];
__device__ uint4 g_b[(NMAX + 1) * 8];
__device__ uint4 g_anchor[(NMAX + 1) * 8];  // 0.1*norm*feat in fp16
__device__ float g_norm[NMAX];
__device__ int   g_deg[NMAX];
__device__ int   g_rowptr[NMAX + 1];        // padded-degree prefix
__device__ int   g_cursor[NMAX];            // seeded = rowptr, bumped by fill
__device__ int   g_srcs[EPAD];
__device__ int   g_part[NTILE];

// ---------------------------------------------------------------- build ----

__global__ void k_zero(int n) {
    int i = blockIdx.x * blockDim.x + threadIdx.x;
    if (i < n) g_deg[i] = 0;
}

__global__ void k_deg(const int* __restrict__ dst, int e) {
    int i = blockIdx.x * blockDim.x + threadIdx.x;
    if (i < e) atomicAdd(&g_deg[dst[i]], 1);
}

// Stage 1: per-tile sums of PADDED degrees.
__global__ void k_scan_part(int n) {
    __shared__ int sh[TILE];
    int t = threadIdx.x;
    int i = blockIdx.x * TILE + t;
    int d = (i < n) ? g_deg[i] : 0;
    sh[t] = (d + 3) & ~3;
    __syncthreads();
    for (int off = TILE >> 1; off > 0; off >>= 1) {
        if (t < off) sh[t] += sh[t + off];
        __syncthreads();
    }
    if (t == 0) g_part[blockIdx.x] = sh[0];
}

// Stage 2: 128 threads, chunk-serial + shuffle scan (2 barriers).
__global__ void k_scan_top(int nb) {
    __shared__ int warp_tot[4];
    int t = threadIdx.x;          // 0..127
    int lane = t & 31;
    int w = t >> 5;
    // each thread serially sums a chunk of 4
    int c[4];
    int s = 0;
    #pragma unroll
    for (int j = 0; j < 4; ++j) {
        int i = t * 4 + j;
        c[j] = (i < nb) ? g_part[i] : 0;
        s += c[j];
    }
    // inclusive shuffle scan of per-thread sums within warp
    int inc = s;
    #pragma unroll
    for (int off = 1; off < 32; off <<= 1) {
        int x = __shfl_up_sync(0xffffffff, inc, off);
        if (lane >= off) inc += x;
    }
    if (lane == 31) warp_tot[w] = inc;
    __syncthreads();
    int woff = 0;
    #pragma unroll
    for (int j = 0; j < 4; ++j) woff += (j < w) ? warp_tot[j] : 0;
    int run = woff + inc - s;     // exclusive prefix of this thread's chunk
    #pragma unroll
    for (int j = 0; j < 4; ++j) {
        int i = t * 4 + j;
        if (i < nb) g_part[i] = run;
        run += c[j];
    }
}

// Stage 3: per-tile scan of padded degrees -> rowptr; cursor = rowptr; norm.
__global__ void k_scan_fin(int n) {
    __shared__ int sh[TILE];
    int t = threadIdx.x;
    int i = blockIdx.x * TILE + t;
    int d    = (i < n) ? g_deg[i] : 0;
    int dpad = (d + 3) & ~3;
    sh[t] = dpad;
    __syncthreads();
    for (int off = 1; off < TILE; off <<= 1) {
        int x = (t >= off) ? sh[t - off] : 0;
        __syncthreads();
        sh[t] += x;
        __syncthreads();
    }
    if (i < n) {
        int rp = sh[t] - dpad + g_part[blockIdx.x];
        g_rowptr[i] = rp;
        g_cursor[i] = rp;                       // seed cursor with rowptr
        g_norm[i]   = rsqrtf(fmaxf((float)d, 1.0f));
        if (i == n - 1) g_rowptr[n] = sh[t] + g_part[blockIdx.x];
    }
}

// One random atomic per edge (cursor pre-seeded with rowptr).
__global__ void k_fill(const int* __restrict__ src,
                       const int* __restrict__ dst, int e) {
    int i = blockIdx.x * blockDim.x + threadIdx.x;
    if (i < e) {
        int pos = atomicAdd(&g_cursor[dst[i]], 1);
        g_srcs[pos] = src[i];
    }
}

// Pad [cursor, rowptr_{i+1}) with dummy row n (cursor == rowptr+deg now).
__global__ void k_pad(int n) {
    int i = blockIdx.x * blockDim.x + threadIdx.x;
    if (i < n) {
        int s  = g_cursor[i];
        int e2 = g_rowptr[i + 1];
        for (int j = s; j < e2; ++j) g_srcs[j] = n;
    }
}

__global__ void k_init(const float* __restrict__ feat, int n) {
    int i = blockIdx.x * blockDim.x + threadIdx.x;   // half2 index
    int tot = (n + 1) * DF2;
    if (i >= tot) return;
    __half2* pa = reinterpret_cast<__half2*>(g_a);
    __half2* pb = reinterpret_cast<__half2*>(g_b);
    __half2* pn = reinterpret_cast<__half2*>(g_anchor);
    int row = i >> 5;
    if (row < n) {
        float nm = g_norm[row];
        float2 f = reinterpret_cast<const float2*>(feat)[i];
        pa[i] = __floats2half2_rn(nm * f.x, nm * f.y);
        pn[i] = __floats2half2_rn(0.1f * nm * f.x, 0.1f * nm * f.y);
    } else {
        __half2 z = __floats2half2_rn(0.f, 0.f);
        pa[i] = z; pb[i] = z; pn[i] = z;
    }
}

// ----------------------------------------------------------------- loop ----

__device__ __forceinline__ void acc_row(const uint4& r, float* acc) {
    const __half2* h = reinterpret_cast<const __half2*>(&r);
    #pragma unroll
    for (int j = 0; j < 4; ++j) {
        float2 w = __half22float2(h[j]);
        acc[2 * j]     += w.x;
        acc[2 * j + 1] += w.y;
    }
}

// One warp per node. Each LDG.128 fetches 4 edge rows (8 lanes/row).
__global__ void __launch_bounds__(256) k_prop(const float* __restrict__ feat,
                       float* __restrict__ out,
                       int n, int flip, int last) {
    int gt   = blockIdx.x * blockDim.x + threadIdx.x;
    int v    = gt >> 5;
    int lane = gt & 31;
    if (v >= n) return;

    const uint4* gin  = flip ? g_b : g_a;
    uint4*       gout = flip ? g_a : g_b;

    int idx = __ldg(&g_rowptr[v]);
    int end = __ldg(&g_rowptr[v + 1]);   // padded: multiple of 4

    int slot = lane >> 3;
    int oct  = lane & 7;

    float acc[8];
    #pragma unroll
    for (int j = 0; j < 8; ++j) acc[j] = 0.f;

    for (; idx + 8 <= end; idx += 8) {
        int s0 = __ldg(&g_srcs[idx + slot]);
        int s1 = __ldg(&g_srcs[idx + 4 + slot]);
        uint4 r0 = gin[s0 * 8 + oct];
        uint4 r1 = gin[s1 * 8 + oct];
        acc_row(r0, acc);
        acc_row(r1, acc);
    }
    if (idx < end) {
        int s0 = __ldg(&g_srcs[idx + slot]);
        uint4 r0 = gin[s0 * 8 + oct];
        acc_row(r0, acc);
    }

    #pragma unroll
    for (int j = 0; j < 8; ++j) {
        acc[j] += __shfl_xor_sync(0xffffffff, acc[j], 8);
        acc[j] += __shfl_xor_sync(0xffffffff, acc[j], 16);
    }

    float nm = __ldg(&g_norm[v]);

    if (!last) {
        if (lane < 8) {
            float c1 = 0.9f * nm * nm;
            uint4 an = g_anchor[v * 8 + oct];
            const __half2* ah = reinterpret_cast<const __half2*>(&an);
            uint4 o;
            __half2* oh = reinterpret_cast<__half2*>(&o);
            #pragma unroll
            for (int j = 0; j < 4; ++j) {
                float2 a2 = __half22float2(ah[j]);
                oh[j] = __floats2half2_rn(c1 * acc[2 * j]     + a2.x,
                                          c1 * acc[2 * j + 1] + a2.y);
            }
            gout[v * 8 + oct] = o;
        }
    } else {
        if (lane < 8) {
            float c1 = 0.9f * nm;
            const float4* fr = reinterpret_cast<const float4*>(feat + v * DF);
            float4* orow = reinterpret_cast<float4*>(out + v * DF);
            float4 f0 = fr[oct * 2];
            float4 f1 = fr[oct * 2 + 1];
            float4 o0, o1;
            o0.x = c1 * acc[0] + 0.1f * f0.x;
            o0.y = c1 * acc[1] + 0.1f * f0.y;
            o0.z = c1 * acc[2] + 0.1f * f0.z;
            o0.w = c1 * acc[3] + 0.1f * f0.w;
            o1.x = c1 * acc[4] + 0.1f * f1.x;
            o1.y = c1 * acc[5] + 0.1f * f1.y;
            o1.z = c1 * acc[6] + 0.1f * f1.z;
            o1.w = c1 * acc[7] + 0.1f * f1.w;
            orow[oct * 2]     = o0;
            orow[oct * 2 + 1] = o1;
        }
    }
}

// ---------------------------------------------------------------- launch ----

extern "C" void kernel_launch(void* const* d_in, const int* in_sizes, int n_in,
                              void* d_out, int out_size) {
    const float* feat = (const float*)d_in[0];
    const int*   src  = (const int*)d_in[1];
    const int*   dst  = (const int*)d_in[2];
    float*       out  = (float*)d_out;

    int n = in_sizes[0] / DF;   // 100000
    int e = in_sizes[1];        // 1000000

    const int T = 256;
    int blk_n = (n + T - 1) / T;
    int blk_e = (e + T - 1) / T;
    int blk_i = ((n + 1) * DF2 + T - 1) / T;
    int blk_p = (n * 32 + T - 1) / T;       // warp per node
    int nb    = (n + TILE - 1) / TILE;

    // CSR build with 4-padded segments
    k_zero<<<blk_n, T>>>(n);
    k_deg<<<blk_e, T>>>(dst, e);
    k_scan_part<<<nb, TILE>>>(n);
    k_scan_top<<<1, 128>>>(nb);
    k_scan_fin<<<nb, TILE>>>(n);
    k_fill<<<blk_e, T>>>(src, dst, e);
    k_pad<<<blk_n, T>>>(n);
    k_init<<<blk_i, T>>>(feat, n);

    // Propagation: ping-pong g_a <-> g_b, final iter writes d_out (fp32).
    for (int t = 0; t < KITER; ++t) {
        int flip = t & 1;
        int last = (t == KITER - 1);
        k_prop<<<blk_p, T>>>(feat, out, n, flip, last);
    }
}